// round 3
// baseline (speedup 1.0000x reference)
#include <cuda_runtime.h>
#include <cuda_bf16.h>

// MulticlassDice: input (8,512,512) int, target (8,512,512) int, weights (8) f32.
// dice[n][c] = (2*inter + 1e-5) / (cnt_in + cnt_tg + 1e-5)
// each_class_dice[c] = mean_n dice[n][c];  total = sum_c w[c]*each_class_dice[c]
// Output assumed: [total, dice[0..7]] (9 f32), with graceful fallbacks.

#define NCLS 8
#define PIX (512 * 512)
#define MAXN 8

// [sample][type(0=in,1=tg,2=inter)][class]
__device__ int g_cnt[MAXN][3][NCLS];
__device__ int g_is64;

// ---------------------------------------------------------------------------
// Kernel 0: zero counters + detect int64-vs-int32 storage.
// Non-negative int64 values < 8 => every odd 32-bit word is zero.
// Sampling 256 odd words: P(false int64 detection | int32 data) = 8^-256 ~ 0.
// Deterministic for fixed inputs -> graph-safe.
// ---------------------------------------------------------------------------
__global__ void k_init_detect(const int* __restrict__ in32) {
    int tid = threadIdx.x;
    if (tid < MAXN * 3 * NCLS) ((int*)g_cnt)[tid] = 0;
    if (tid < 32) {
        int nz = 0;
#pragma unroll
        for (int i = 0; i < 8; i++) {
            int idx = 2 * (tid + 32 * i) + 1;  // odd 32-bit word
            nz |= in32[idx];
        }
        unsigned mask = __ballot_sync(0xffffffffu, nz != 0);
        if (tid == 0) g_is64 = (mask == 0u) ? 1 : 0;
    }
}

// ---------------------------------------------------------------------------
// Kernel 1: per-(sample,class) histograms.
// grid.y = sample. Register counters -> REDUX warp reduce -> smem -> gmem atomics.
// ---------------------------------------------------------------------------
__global__ __launch_bounds__(256) void k_count(const int* __restrict__ inB,
                                               const int* __restrict__ tgB) {
    const int n = blockIdx.y;
    const bool is64 = (g_is64 != 0);

    int cin[NCLS], ctg[NCLS], cxx[NCLS];
#pragma unroll
    for (int c = 0; c < NCLS; c++) { cin[c] = 0; ctg[c] = 0; cxx[c] = 0; }

    const int stride = gridDim.x * blockDim.x;
    const int tid0 = blockIdx.x * blockDim.x + threadIdx.x;

    if (is64) {
        // 2 pixels per int4 (low halves at .x and .z)
        const int4* a = (const int4*)inB + (size_t)n * (PIX / 2);
        const int4* b = (const int4*)tgB + (size_t)n * (PIX / 2);
        for (int i = tid0; i < PIX / 2; i += stride) {
            int4 va = a[i], vb = b[i];
#pragma unroll
            for (int c = 0; c < NCLS; c++) {
                int a0 = (va.x == c), a1 = (va.z == c);
                int b0 = (vb.x == c), b1 = (vb.z == c);
                cin[c] += a0 + a1;
                ctg[c] += b0 + b1;
                cxx[c] += (a0 & b0) + (a1 & b1);
            }
        }
    } else {
        // 4 pixels per int4
        const int4* a = (const int4*)inB + (size_t)n * (PIX / 4);
        const int4* b = (const int4*)tgB + (size_t)n * (PIX / 4);
        for (int i = tid0; i < PIX / 4; i += stride) {
            int4 va = a[i], vb = b[i];
#pragma unroll
            for (int c = 0; c < NCLS; c++) {
                int a0 = (va.x == c), a1 = (va.y == c), a2 = (va.z == c), a3 = (va.w == c);
                int b0 = (vb.x == c), b1 = (vb.y == c), b2 = (vb.z == c), b3 = (vb.w == c);
                cin[c] += a0 + a1 + a2 + a3;
                ctg[c] += b0 + b1 + b2 + b3;
                cxx[c] += (a0 & b0) + (a1 & b1) + (a2 & b2) + (a3 & b3);
            }
        }
    }

    // Warp reduce (REDUX.SUM on sm_80+)
#pragma unroll
    for (int c = 0; c < NCLS; c++) {
        cin[c] = __reduce_add_sync(0xffffffffu, cin[c]);
        ctg[c] = __reduce_add_sync(0xffffffffu, ctg[c]);
        cxx[c] = __reduce_add_sync(0xffffffffu, cxx[c]);
    }

    __shared__ int s[3 * NCLS];
    if (threadIdx.x < 3 * NCLS) s[threadIdx.x] = 0;
    __syncthreads();

    if ((threadIdx.x & 31) == 0) {
#pragma unroll
        for (int c = 0; c < NCLS; c++) {
            atomicAdd(&s[0 * NCLS + c], cin[c]);
            atomicAdd(&s[1 * NCLS + c], ctg[c]);
            atomicAdd(&s[2 * NCLS + c], cxx[c]);
        }
    }
    __syncthreads();

    if (threadIdx.x < 3 * NCLS) {
        atomicAdd(&((int*)g_cnt)[n * (3 * NCLS) + threadIdx.x], s[threadIdx.x]);
    }
}

// ---------------------------------------------------------------------------
// Kernel 2: dice + reduction + output write (covers all out_size elements).
// ---------------------------------------------------------------------------
__global__ void k_finalize(const float* __restrict__ w, float* __restrict__ out,
                           int out_size, int N) {
    __shared__ float dice[MAXN][NCLS];
    __shared__ float mean_c[NCLS];
    __shared__ float total_s;
    const int tid = threadIdx.x;  // 64 threads
    const int n = tid / NCLS, c = tid % NCLS;

    if (n < N) {
        float inter = (float)g_cnt[n][2][c];
        float sums = (float)(g_cnt[n][0][c] + g_cnt[n][1][c]);
        dice[n][c] = (2.0f * inter + 1e-5f) / (sums + 1e-5f);
    }
    __syncthreads();

    if (tid < NCLS) {
        float m = 0.0f;
        for (int i = 0; i < N; i++) m += dice[i][tid];
        mean_c[tid] = m / (float)N;
    }
    __syncthreads();

    if (tid == 0) {
        float t = 0.0f;
        for (int cc = 0; cc < NCLS; cc++) t += w[cc] * mean_c[cc];
        total_s = t;
    }
    __syncthreads();

    for (int i = tid; i < out_size; i += blockDim.x) {
        float v;
        if (out_size >= NCLS + 1) {
            // [total, mean_c[0..7], pad...]
            v = (i == 0) ? total_s : (i <= NCLS ? mean_c[i - 1] : 0.0f);
        } else if (out_size == NCLS) {
            // just the per-class dice
            v = mean_c[i];
        } else {
            // scalar-ish output: total first, then per-class if room
            v = (i == 0) ? total_s : (i - 1 < NCLS ? mean_c[i - 1] : 0.0f);
        }
        out[i] = v;
    }
}

// ---------------------------------------------------------------------------
extern "C" void kernel_launch(void* const* d_in, const int* in_sizes, int n_in,
                              void* d_out, int out_size) {
    const int* inB = (const int*)d_in[0];
    const int* tgB = (const int*)d_in[1];
    const float* w = (const float*)d_in[2];
    float* out = (float*)d_out;

    int N = in_sizes[0] / PIX;
    if (N < 1) N = 1;
    if (N > MAXN) N = MAXN;

    k_init_detect<<<1, 256>>>(inB);

    dim3 grid(96, N);
    k_count<<<grid, 256>>>(inB, tgB);

    k_finalize<<<1, 64>>>(w, out, out_size, N);
}